// round 4
// baseline (speedup 1.0000x reference)
#include <cuda_runtime.h>
#include <math.h>

// Problem constants (B=64, C=1024, Q=128, D=128)
#define NB 64
#define NC 1024
#define NQ 128
#define ND 128
#define TC 64          // context rows per CTA
#define PQ 132         // Qrow pitch (floats)
#define PA 132         // Ac pitch
#define PP 264         // P2 pitch (duplicated pairs: 2*128 + 8 pad)

// smem float offsets
#define OFF_A  0
#define OFF_Q  (TC*PA)                 // 8448
#define OFF_P  (OFF_Q + NQ*PQ)         // 25344
#define OFF_CT (OFF_P + TC*PP)         // 42240
#define OFF_QT (OFF_CT + TC)           // 42304
#define SMEM_FLOATS (OFF_QT + NQ)      // 42432 -> 169728 bytes

__device__ float g_m[NB * NC];
__device__ float g_q2c[NB * ND];

__device__ __forceinline__ void ffma2(unsigned long long &acc,
                                      unsigned long long a,
                                      unsigned long long b) {
    asm("fma.rn.f32x2 %0, %1, %2, %0;" : "+l"(acc) : "l"(a), "l"(b));
}

__device__ __forceinline__ float2 up2(unsigned long long u) {
    float2 f;
    f.x = __int_as_float((int)(unsigned)(u & 0xffffffffULL));
    f.y = __int_as_float((int)(unsigned)(u >> 32));
    return f;
}

extern __shared__ float sm[];

__global__ void __launch_bounds__(256, 1)
k_main(const float* __restrict__ ctx, const float* __restrict__ qry,
       const float* __restrict__ W, const float* __restrict__ mask,
       float* __restrict__ out) {
    const int b = blockIdx.y;
    const int c0 = blockIdx.x * TC;
    const int tid = threadIdx.x;

    const float* ctxb = ctx + ((size_t)(b * NC + c0)) * ND;
    const float* qryb = qry + ((size_t)b) * NQ * ND;

    // ---- Stage Qrow (row-major [q][d]) + q_term + mask fold ----
    {
        const int q = tid >> 1, h = tid & 1;
        const float* src = qryb + q * ND + h * 64;
        float qt = 0.f;
#pragma unroll
        for (int i = 0; i < 16; i++) {
            float4 v = ((const float4*)src)[i];
            int d = h * 64 + i * 4;
            qt += v.x * W[ND + d] + v.y * W[ND + d + 1] +
                  v.z * W[ND + d + 2] + v.w * W[ND + d + 3];
            *(float4*)&sm[OFF_Q + q * PQ + d] = v;
        }
        qt += __shfl_xor_sync(0xffffffffu, qt, 1);
        if (h == 0)
            sm[OFF_QT + q] = qt + (1.0f - mask[b * NQ + q]) * (-1000000000.0f);
    }
    // ---- Stage Ac_s = context * w_s  +  c_term ----
    {
        const int c = tid >> 2, qt4 = tid & 3;
        const float* src = ctxb + c * ND + qt4 * 32;
        float ct = 0.f;
#pragma unroll
        for (int i = 0; i < 8; i++) {
            float4 v = ((const float4*)src)[i];
            int d = qt4 * 32 + i * 4;
            ct += v.x * W[d] + v.y * W[d + 1] + v.z * W[d + 2] + v.w * W[d + 3];
            float4 s4;
            s4.x = v.x * W[2 * ND + d];
            s4.y = v.y * W[2 * ND + d + 1];
            s4.z = v.z * W[2 * ND + d + 2];
            s4.w = v.w * W[2 * ND + d + 3];
            *(float4*)&sm[OFF_A + c * PA + d] = s4;
        }
        ct += __shfl_xor_sync(0xffffffffu, ct, 1);
        ct += __shfl_xor_sync(0xffffffffu, ct, 2);
        if (qt4 == 0) sm[OFF_CT + c] = ct;
    }
    __syncthreads();

    const int tx = tid & 15;   // q / d dimension
    const int ty = tid >> 4;   // c dimension

    // ---- S GEMM: 4c x 8q per thread, d-pair packed FFMA2 ----
    unsigned long long acc[4][8];
#pragma unroll
    for (int i = 0; i < 4; i++)
#pragma unroll
        for (int j = 0; j < 8; j++) acc[i][j] = 0ULL;

#pragma unroll 2
    for (int kk = 0; kk < ND; kk += 4) {
        ulonglong2 a[4];
#pragma unroll
        for (int i = 0; i < 4; i++)
            a[i] = *(const ulonglong2*)&sm[OFF_A + (ty * 4 + i) * PA + kk];
        ulonglong2 bq[8];
#pragma unroll
        for (int j = 0; j < 8; j++)
            bq[j] = *(const ulonglong2*)&sm[OFF_Q + (tx + 16 * j) * PQ + kk];
#pragma unroll
        for (int i = 0; i < 4; i++)
#pragma unroll
            for (int j = 0; j < 8; j++) {
                ffma2(acc[i][j], a[i].x, bq[j].x);
                ffma2(acc[i][j], a[i].y, bq[j].y);
            }
    }

    // ---- Softmax over q (in registers, 16-lane shuffle groups) ----
    float ctv[4], qv[8];
#pragma unroll
    for (int i = 0; i < 4; i++) ctv[i] = sm[OFF_CT + ty * 4 + i];
#pragma unroll
    for (int j = 0; j < 8; j++) qv[j] = sm[OFF_QT + tx + 16 * j];

#pragma unroll
    for (int i = 0; i < 4; i++) {
        float s[8];
        float mx = -3.4e38f;
#pragma unroll
        for (int j = 0; j < 8; j++) {
            float2 f = up2(acc[i][j]);
            s[j] = f.x + f.y + ctv[i] + qv[j];
            mx = fmaxf(mx, s[j]);
        }
        mx = fmaxf(mx, __shfl_xor_sync(0xffffffffu, mx, 1));
        mx = fmaxf(mx, __shfl_xor_sync(0xffffffffu, mx, 2));
        mx = fmaxf(mx, __shfl_xor_sync(0xffffffffu, mx, 4));
        mx = fmaxf(mx, __shfl_xor_sync(0xffffffffu, mx, 8));
        float ee[8], sum = 0.f;
#pragma unroll
        for (int j = 0; j < 8; j++) { ee[j] = __expf(s[j] - mx); sum += ee[j]; }
        sum += __shfl_xor_sync(0xffffffffu, sum, 1);
        sum += __shfl_xor_sync(0xffffffffu, sum, 2);
        sum += __shfl_xor_sync(0xffffffffu, sum, 4);
        sum += __shfl_xor_sync(0xffffffffu, sum, 8);
        float r = __fdividef(1.0f, sum);
#pragma unroll
        for (int j = 0; j < 8; j++) {
            float p = ee[j] * r;
            float2 pp; pp.x = p; pp.y = p;  // duplicated pair for FFMA2
            *(float2*)&sm[OFF_P + (ty * 4 + i) * PP + 2 * (tx + 16 * j)] = pp;
        }
        if (tx == 0) g_m[b * NC + c0 + ty * 4 + i] = mx;
    }
    __syncthreads();

    // ---- c2q GEMM: 4c x 8d per thread (d = 4tx..4tx+3 and 64+4tx..), q-pair FFMA2 ----
    unsigned long long ca[4][4];
#pragma unroll
    for (int i = 0; i < 4; i++)
#pragma unroll
        for (int p = 0; p < 4; p++) ca[i][p] = 0ULL;

#pragma unroll 2
    for (int q = 0; q < NQ; q++) {
        ulonglong2 b0 = *(const ulonglong2*)&sm[OFF_Q + q * PQ + 4 * tx];
        ulonglong2 b1 = *(const ulonglong2*)&sm[OFF_Q + q * PQ + 64 + 4 * tx];
#pragma unroll
        for (int i = 0; i < 4; i++) {
            unsigned long long a =
                *(const unsigned long long*)&sm[OFF_P + (ty * 4 + i) * PP + 2 * q];
            ffma2(ca[i][0], a, b0.x);
            ffma2(ca[i][1], a, b0.y);
            ffma2(ca[i][2], a, b1.x);
            ffma2(ca[i][3], a, b1.y);
        }
    }

    // ---- Epilogue: chunks 1..3 ----
#pragma unroll
    for (int i = 0; i < 4; i++) {
        int c = c0 + ty * 4 + i;
        const float4* crow = (const float4*)(ctx + ((size_t)(b * NC + c)) * ND);
        float4 x0 = crow[tx];
        float4 x1 = crow[16 + tx];
        float2 y0 = up2(ca[i][0]), y1 = up2(ca[i][1]);
        float2 y2 = up2(ca[i][2]), y3 = up2(ca[i][3]);
        float4 cq0 = make_float4(y0.x, y0.y, y1.x, y1.y);
        float4 cq1 = make_float4(y2.x, y2.y, y3.x, y3.y);
        float* ob = out + ((size_t)(b * NC + c)) * (4 * ND);
        *(float4*)&ob[4 * tx] = x0;
        *(float4*)&ob[64 + 4 * tx] = x1;
        *(float4*)&ob[ND + 4 * tx] = cq0;
        *(float4*)&ob[ND + 64 + 4 * tx] = cq1;
        float4 m0 = make_float4(x0.x * cq0.x, x0.y * cq0.y, x0.z * cq0.z, x0.w * cq0.w);
        float4 m1 = make_float4(x1.x * cq1.x, x1.y * cq1.y, x1.z * cq1.z, x1.w * cq1.w);
        *(float4*)&ob[2 * ND + 4 * tx] = m0;
        *(float4*)&ob[2 * ND + 64 + 4 * tx] = m1;
    }
}

__global__ void __launch_bounds__(256, 4)
k_q2c(const float* __restrict__ ctx) {
    __shared__ float sp[NC];
    __shared__ float sr[8];
    __shared__ float sr2[8];
    __shared__ float spart[256];
    const int b = blockIdx.x;
    const int tid = threadIdx.x;

    float v[4];
    float mx = -3.4e38f;
#pragma unroll
    for (int k = 0; k < 4; k++) {
        v[k] = g_m[b * NC + tid + 256 * k];
        mx = fmaxf(mx, v[k]);
    }
#pragma unroll
    for (int o = 16; o > 0; o >>= 1)
        mx = fmaxf(mx, __shfl_xor_sync(0xffffffffu, mx, o));
    if ((tid & 31) == 0) sr[tid >> 5] = mx;
    __syncthreads();
    float M = sr[0];
#pragma unroll
    for (int w = 1; w < 8; w++) M = fmaxf(M, sr[w]);

    float s = 0.f;
#pragma unroll
    for (int k = 0; k < 4; k++) {
        float e = __expf(v[k] - M);
        sp[tid + 256 * k] = e;
        s += e;
    }
#pragma unroll
    for (int o = 16; o > 0; o >>= 1)
        s += __shfl_xor_sync(0xffffffffu, s, o);
    if ((tid & 31) == 0) sr2[tid >> 5] = s;
    __syncthreads();
    float T = 0.f;
#pragma unroll
    for (int w = 0; w < 8; w++) T += sr2[w];
    float rs = __fdividef(1.0f, T);

    const int d = tid & 127, half = tid >> 7;
    const float* cb = ctx + ((size_t)b) * NC * ND + ((size_t)half) * 512 * ND + d;
    float a0 = 0.f, a1 = 0.f, a2 = 0.f, a3 = 0.f;
    const int cbase = half * 512;
#pragma unroll 4
    for (int c = 0; c < 512; c += 4) {
        a0 += sp[cbase + c + 0] * cb[(size_t)(c + 0) * ND];
        a1 += sp[cbase + c + 1] * cb[(size_t)(c + 1) * ND];
        a2 += sp[cbase + c + 2] * cb[(size_t)(c + 2) * ND];
        a3 += sp[cbase + c + 3] * cb[(size_t)(c + 3) * ND];
    }
    spart[tid] = (a0 + a1) + (a2 + a3);
    __syncthreads();
    if (tid < 128)
        g_q2c[b * ND + tid] = (spart[tid] + spart[tid + 128]) * rs;
}

__global__ void __launch_bounds__(256, 4)
k_out4(const float* __restrict__ ctx, float* __restrict__ out) {
    __shared__ float q2[ND];
    const int b = blockIdx.y;
    const int r0 = blockIdx.x * 16;
    if (threadIdx.x < ND) q2[threadIdx.x] = g_q2c[b * ND + threadIdx.x];
    __syncthreads();
    for (int vid = threadIdx.x; vid < 16 * 32; vid += 256) {
        int r = vid >> 5;
        int d4 = (vid & 31) * 4;
        int c = r0 + r;
        float4 x = *(const float4*)&ctx[((size_t)(b * NC + c)) * ND + d4];
        float4 qv = *(const float4*)&q2[d4];
        float4 o = make_float4(x.x * qv.x, x.y * qv.y, x.z * qv.z, x.w * qv.w);
        *(float4*)&out[((size_t)(b * NC + c)) * (4 * ND) + 3 * ND + d4] = o;
    }
}

extern "C" void kernel_launch(void* const* d_in, const int* in_sizes, int n_in,
                              void* d_out, int out_size) {
    const float* ctx  = (const float*)d_in[0];
    const float* qry  = (const float*)d_in[1];
    const float* W    = (const float*)d_in[2];
    const float* mask = (const float*)d_in[3];
    float* out = (float*)d_out;

    cudaFuncSetAttribute(k_main, cudaFuncAttributeMaxDynamicSharedMemorySize,
                         SMEM_FLOATS * (int)sizeof(float));

    k_main<<<dim3(NC / TC, NB), 256, SMEM_FLOATS * sizeof(float)>>>(ctx, qry, W, mask, out);
    k_q2c<<<NB, 256>>>(ctx);
    k_out4<<<dim3(NC / 16, NB), 256>>>(ctx, out);
}